// round 9
// baseline (speedup 1.0000x reference)
#include <cuda_runtime.h>
#include <cstdint>

// out[b,f] = -( sum_w x[b,w,f] * W[f,w] + bias[f] )
// x: [512, 5, 25000] f32   W: [25000, 5] f32   bias: [25000] f32   out: [512, 25000] f32
//
// R9: persistent CTAs with STATIC, barrier-free schedule (R8's dynamic queue
// regressed because its per-item __syncthreads broke the load stream).
// 608 CTAs; CTA c owns contiguous items [c*6400/608, (c+1)*6400/608) in
// y-fastest order (item = xblk*256 + y), so W/bias smem columns reload at
// most twice per CTA, detected per-thread with no sync.
// Per-item body identical to R6: 10 independent LDG.128 (.cs), FMA from
// conflict-free smem columns, 2 STG.128 (.cs).

#define F_DIM    25000
#define WS       5
#define B_DIM    512
#define B_PER    2
#define NTHREADS 256
#define F4_DIM   (F_DIM / 4)            // 6250
#define XBLKS    25
#define YBLKS    (B_DIM / B_PER)         // 256
#define N_ITEMS  (XBLKS * YBLKS)         // 6400
#define N_CTAS   608                     // 152 SMs x 4 CTAs

__global__ __launch_bounds__(NTHREADS, 4)
void ocsvm_kernel(const float* __restrict__ x,
                  const float* __restrict__ W,
                  const float* __restrict__ bias,
                  float* __restrict__ out) {
    // w_s[0..19][tid] = W for this thread's 4 features, w_s[20..23][tid] = -bias.
    // 4B stride across threads -> bank = tid%32: conflict-free; each thread
    // touches only its own column, so no synchronization is ever needed.
    __shared__ float w_s[4 * WS + 4][NTHREADS];

    const int tid = threadIdx.x;
    const unsigned int cta = blockIdx.x;

    // Balanced contiguous chunk: 10 or 11 items.
    const unsigned int item_beg = (unsigned int)(((unsigned long long)cta * N_ITEMS) / N_CTAS);
    const unsigned int item_end = (unsigned int)(((unsigned long long)(cta + 1) * N_ITEMS) / N_CTAS);

    int cur_xblk = -1;

#pragma unroll 1
    for (unsigned int item = item_beg; item < item_end; item++) {
        const int xblk = (int)(item / YBLKS);   // y-fastest: xblk constant ~256 items
        const int y    = (int)(item % YBLKS);
        const int f4   = xblk * NTHREADS + tid;
        if (f4 >= F4_DIM) continue;             // only last xblk partially valid
        const int f = f4 * 4;

        if (xblk != cur_xblk) {
            cur_xblk = xblk;
            const float4* W4 = reinterpret_cast<const float4*>(W) + (size_t)f4 * WS;
#pragma unroll
            for (int k = 0; k < WS; k++) {
                float4 q = __ldg(W4 + k);
                w_s[4 * k + 0][tid] = q.x;
                w_s[4 * k + 1][tid] = q.y;
                w_s[4 * k + 2][tid] = q.z;
                w_s[4 * k + 3][tid] = q.w;
            }
            const float4 bb = __ldg(reinterpret_cast<const float4*>(bias + f));
            w_s[20][tid] = -bb.x;
            w_s[21][tid] = -bb.y;
            w_s[22][tid] = -bb.z;
            w_s[23][tid] = -bb.w;
        }

        const int b0 = y * B_PER;

        // All 10 streaming loads in flight before any math.
        float4 xv[B_PER][WS];
#pragma unroll
        for (int bi = 0; bi < B_PER; bi++) {
            const size_t base = (size_t)(b0 + bi) * (WS * F_DIM) + f;
#pragma unroll
            for (int wi = 0; wi < WS; wi++) {
                xv[bi][wi] = __ldcs(reinterpret_cast<const float4*>(
                    x + base + (size_t)wi * F_DIM));
            }
        }

#pragma unroll
        for (int bi = 0; bi < B_PER; bi++) {
            float a0 = w_s[20][tid], a1 = w_s[21][tid];
            float a2 = w_s[22][tid], a3 = w_s[23][tid];
#pragma unroll
            for (int wi = 0; wi < WS; wi++) {
                a0 = fmaf(-xv[bi][wi].x, w_s[0 * WS + wi][tid], a0);
                a1 = fmaf(-xv[bi][wi].y, w_s[1 * WS + wi][tid], a1);
                a2 = fmaf(-xv[bi][wi].z, w_s[2 * WS + wi][tid], a2);
                a3 = fmaf(-xv[bi][wi].w, w_s[3 * WS + wi][tid], a3);
            }
            float4 o; o.x = a0; o.y = a1; o.z = a2; o.w = a3;
            __stcs(reinterpret_cast<float4*>(out + (size_t)(b0 + bi) * F_DIM + f), o);
        }
    }
}

extern "C" void kernel_launch(void* const* d_in, const int* in_sizes, int n_in,
                              void* d_out, int out_size) {
    const float* x    = (const float*)d_in[0];
    const float* W    = (const float*)d_in[1];
    const float* bias = (const float*)d_in[2];
    float* out        = (float*)d_out;

    ocsvm_kernel<<<N_CTAS, NTHREADS>>>(x, W, bias, out);
}

// round 10
// speedup vs baseline: 1.0841x; 1.0841x over previous
#include <cuda_runtime.h>
#include <cstdint>

// out[b,f] = -( sum_w x[b,w,f] * W[f,w] + bias[f] )
// x: [512, 5, 25000] f32   W: [25000, 5] f32   bias: [25000] f32   out: [512, 25000] f32
//
// R10 = R6 (best: 44.8us) with one change: the 10 x streaming loads are
// issued BEFORE the W/bias loads at block start, so the dominant x stream
// starts immediately and the W latency hides behind it. Everything else is
// identical: 25x256 grid, B_PER=2, 4 CTAs/SM, 10 independent LDG.128 (.cs),
// W/bias in conflict-free per-thread SMEM columns, STG.128 (.cs).

#define F_DIM    25000
#define WS       5
#define B_DIM    512
#define B_PER    2
#define NTHREADS 256
#define F4_DIM   (F_DIM / 4)   // 6250

__global__ __launch_bounds__(NTHREADS, 4)
void ocsvm_kernel(const float* __restrict__ x,
                  const float* __restrict__ W,
                  const float* __restrict__ bias,
                  float* __restrict__ out) {
    // w_s[p][tid] holds W[(f + p/5)*5 + p%5]; w_s[20..23][tid] = -bias.
    // 4B stride across threads -> bank = tid%32: conflict-free; each thread
    // touches only its own column, so no sync is needed.
    __shared__ float w_s[4 * WS + 4][NTHREADS];

    const int tid = threadIdx.x;
    const int f4  = blockIdx.x * NTHREADS + tid;
    if (f4 >= F4_DIM) return;
    const int f = f4 * 4;

    const int b0 = blockIdx.y * B_PER;

    // ---- Issue the dominant x stream FIRST: 10 independent LDG.128. ----
    float4 xv[B_PER][WS];
#pragma unroll
    for (int bi = 0; bi < B_PER; bi++) {
        const size_t base = (size_t)(b0 + bi) * (WS * F_DIM) + f;
#pragma unroll
        for (int wi = 0; wi < WS; wi++) {
            xv[bi][wi] = __ldcs(reinterpret_cast<const float4*>(x + base + (size_t)wi * F_DIM));
        }
    }

    // ---- W/bias load lands while x is in flight. ----
    {
        const float4* W4 = reinterpret_cast<const float4*>(W) + (size_t)f4 * WS;
#pragma unroll
        for (int k = 0; k < WS; k++) {
            float4 q = __ldg(W4 + k);
            w_s[4 * k + 0][tid] = q.x;
            w_s[4 * k + 1][tid] = q.y;
            w_s[4 * k + 2][tid] = q.z;
            w_s[4 * k + 3][tid] = q.w;
        }
        const float4 bb = __ldg(reinterpret_cast<const float4*>(bias + f));
        w_s[20][tid] = -bb.x;
        w_s[21][tid] = -bb.y;
        w_s[22][tid] = -bb.z;
        w_s[23][tid] = -bb.w;
    }

#pragma unroll
    for (int bi = 0; bi < B_PER; bi++) {
        float a0 = w_s[20][tid], a1 = w_s[21][tid];
        float a2 = w_s[22][tid], a3 = w_s[23][tid];
#pragma unroll
        for (int wi = 0; wi < WS; wi++) {
            a0 = fmaf(-xv[bi][wi].x, w_s[0 * WS + wi][tid], a0);
            a1 = fmaf(-xv[bi][wi].y, w_s[1 * WS + wi][tid], a1);
            a2 = fmaf(-xv[bi][wi].z, w_s[2 * WS + wi][tid], a2);
            a3 = fmaf(-xv[bi][wi].w, w_s[3 * WS + wi][tid], a3);
        }
        float4 o; o.x = a0; o.y = a1; o.z = a2; o.w = a3;
        __stcs(reinterpret_cast<float4*>(out + (size_t)(b0 + bi) * F_DIM + f), o);
    }
}

extern "C" void kernel_launch(void* const* d_in, const int* in_sizes, int n_in,
                              void* d_out, int out_size) {
    const float* x    = (const float*)d_in[0];
    const float* W    = (const float*)d_in[1];
    const float* bias = (const float*)d_in[2];
    float* out        = (float*)d_out;

    dim3 grid((F4_DIM + NTHREADS - 1) / NTHREADS,   // 25
              B_DIM / B_PER);                        // 256
    ocsvm_kernel<<<grid, NTHREADS>>>(x, W, bias, out);
}